// round 14
// baseline (speedup 1.0000x reference)
#include <cuda_runtime.h>
#include <cstdint>
#include <math.h>

#define BS 4
#define LQ 12240
#define EMBED 256
#define HEADS 8
#define MTOT (BS * LQ)   // 48960

// ---------------- scratch (no cudaMalloc allowed) ----------------
__device__ float g_v[(size_t)MTOT * 256];     // projected value [b,Lv,H,32]
__device__ float g_off[(size_t)MTOT * 256];   // offsets [b,q,H,L,P,2]
__device__ float g_attn[(size_t)MTOT * 128];  // attn logits [b,q,H,16]
__device__ float g_acc[(size_t)MTOT * 256];   // sampled acc [b,q,H,32]

// packed paired-tf32 weights: [kt][slot 0..7][n], slot s -> k-pair
// (kt*16 + (s>>2)*8 + (s&3), +4)
__device__ uint2 g_Wval_p[16 * 8 * 256];
__device__ uint2 g_Woff_p[16 * 8 * 256];
__device__ uint2 g_Wattn_p[16 * 8 * 128];
__device__ uint2 g_Wout_p[16 * 8 * 256];

__device__ __forceinline__ uint32_t to_tf32(float x) {
    uint32_t h;
    asm("cvt.rna.tf32.f32 %0, %1;" : "=r"(h) : "f"(x));
    return h;
}

__device__ __forceinline__ void mma_tf32(float* d, const uint32_t* a, const uint32_t* b) {
    asm volatile(
        "mma.sync.aligned.m16n8k8.row.col.f32.tf32.tf32.f32 "
        "{%0,%1,%2,%3}, {%4,%5,%6,%7}, {%8,%9}, {%0,%1,%2,%3};"
        : "+f"(d[0]), "+f"(d[1]), "+f"(d[2]), "+f"(d[3])
        : "r"(a[0]), "r"(a[1]), "r"(a[2]), "r"(a[3]), "r"(b[0]), "r"(b[1]));
}

__device__ __forceinline__ void cp_async16(void* smem, const void* gmem) {
    uint32_t s = (uint32_t)__cvta_generic_to_shared(smem);
    asm volatile("cp.async.ca.shared.global [%0], [%1], 16;" :: "r"(s), "l"(gmem));
}

// ---------------- weight pre-pack ----------------
__global__ __launch_bounds__(256) void pack_kernel(
    const float* __restrict__ W, uint2* __restrict__ Wp, int N, int K)
{
    const int idx = blockIdx.x * 256 + threadIdx.x;
    const int total = (K / 16) * 8 * N;
    if (idx >= total) return;
    const int n = idx % N;
    const int s = (idx / N) & 7;
    const int kt = idx / (N * 8);
    const int klo = kt * 16 + (s >> 2) * 8 + (s & 3);
    Wp[idx] = make_uint2(to_tf32(W[(size_t)klo * N + n]),
                         to_tf32(W[(size_t)(klo + 4) * N + n]));
}

#define ASTRIDE 20     // A floats per row (16 + 4 pad): conflict-free frag LDS
#define BSTRIDE 136    // B uint2 per slot row (128 + 8 pad): conflict-free LDS.64

// ---------------- GEMM body: A cp.async raw fp32; B cp.async packed tf32 ---
__device__ __forceinline__ void gemm_body(
    const float* __restrict__ A, const uint2* __restrict__ Bp,
    const float* __restrict__ bias, float* __restrict__ C,
    int M, int N, int K, int bm, int bn,
    float (*As)[128][ASTRIDE], uint2 (*Bs)[8][BSTRIDE])
{
    const int tid = threadIdx.x;
    const int warp = tid >> 5;
    const int lane = tid & 31;
    const int wm = (warp >> 1) * 32;
    const int wn = (warp & 1) * 64;
    const int g = lane >> 2;           // 0..7
    const int tig = lane & 3;          // 0..3

    // A fill: thread cp.asyncs 32B of row (tid>>1) at k-offset (tid&1)*8
    const int a_row = tid >> 1;
    const int a_half = tid & 1;
    int a_grow = bm + a_row; if (a_grow >= M) a_grow = M - 1;
    const float* Ag = A + (size_t)a_grow * K + a_half * 8;

    // B fill: slot = tid>>5, qcol = (lane)*4 -> 32B (4 uint2) per thread
    const int b_slot = tid >> 5;       // 0..7
    const int b_qcol = lane * 4;       // 0..124
    const uint2* Bgp = Bp + (size_t)b_slot * N + bn + b_qcol;

#define FILL(kt, stg) do { \
        const float* ap = Ag + (kt) * 16; \
        cp_async16(&As[stg][a_row][a_half * 8], ap); \
        cp_async16(&As[stg][a_row][a_half * 8 + 4], ap + 4); \
        const uint2* bp = Bgp + (size_t)(kt) * 8 * N; \
        cp_async16(&Bs[stg][b_slot][b_qcol], bp); \
        cp_async16(&Bs[stg][b_slot][b_qcol + 2], bp + 2); \
        asm volatile("cp.async.commit_group;"); \
    } while (0)

    float acc[2][8][4];
#pragma unroll
    for (int i = 0; i < 2; i++)
#pragma unroll
        for (int j = 0; j < 8; j++)
#pragma unroll
            for (int r = 0; r < 4; r++) acc[i][j][r] = 0.f;

    const int NT = K / 16;
    FILL(0, 0);
    FILL(1, 1);

    int st = 0;
    for (int kt = 0; kt < NT; kt++) {
        if (kt + 1 < NT) {
            asm volatile("cp.async.wait_group 1;");
        } else {
            asm volatile("cp.async.wait_group 0;");
        }
        __syncthreads();

        if (kt + 2 < NT) {
            int fs = st - 1; if (fs < 0) fs += 3;   // (kt+2) % 3
            FILL(kt + 2, fs);
        }

#pragma unroll
        for (int ks = 0; ks < 2; ks++) {
            const int k8 = ks * 8;
            const int kp = ks * 4 + tig;
            uint32_t af[2][4];
#pragma unroll
            for (int mt = 0; mt < 2; mt++) {
                const int mb = wm + mt * 16;
                af[mt][0] = to_tf32(As[st][mb + g][k8 + tig]);
                af[mt][1] = to_tf32(As[st][mb + g + 8][k8 + tig]);
                af[mt][2] = to_tf32(As[st][mb + g][k8 + tig + 4]);
                af[mt][3] = to_tf32(As[st][mb + g + 8][k8 + tig + 4]);
            }
            uint32_t bf[8][2];
#pragma unroll
            for (int nt = 0; nt < 8; nt++) {
                uint2 ub = Bs[st][kp][wn + nt * 8 + g];
                bf[nt][0] = ub.x; bf[nt][1] = ub.y;
            }
#pragma unroll
            for (int mt = 0; mt < 2; mt++)
#pragma unroll
                for (int nt = 0; nt < 8; nt++)
                    mma_tf32(acc[mt][nt], af[mt], bf[nt]);
        }

        st = st + 1 == 3 ? 0 : st + 1;
    }

    // epilogue: D + bias -> C
#pragma unroll
    for (int nt = 0; nt < 8; nt++) {
        const int n = bn + wn + nt * 8 + 2 * tig;
        const float b0 = bias[n];
        const float b1 = bias[n + 1];
#pragma unroll
        for (int mt = 0; mt < 2; mt++) {
            const int m0 = bm + wm + mt * 16 + g;
            if (m0 < M) {
                float2 o = make_float2(acc[mt][nt][0] + b0, acc[mt][nt][1] + b1);
                *(float2*)&C[(size_t)m0 * N + n] = o;
            }
            const int m1 = m0 + 8;
            if (m1 < M) {
                float2 o = make_float2(acc[mt][nt][2] + b0, acc[mt][nt][3] + b1);
                *(float2*)&C[(size_t)m1 * N + n] = o;
            }
        }
    }
#undef FILL
}

// Standalone GEMM (output projection).
__global__ __launch_bounds__(256, 2) void gemm_tf32_kernel(
    const float* __restrict__ A, const uint2* __restrict__ Bp,
    const float* __restrict__ bias, float* __restrict__ C,
    int M, int N, int K)
{
    __shared__ float As[3][128][ASTRIDE];
    __shared__ uint2 Bs[3][8][BSTRIDE];
    gemm_body(A, Bp, bias, C, M, N, K, blockIdx.y * 128, blockIdx.x * 128, As, Bs);
}

// Merged projection kernel: three independent input GEMMs in one launch.
__global__ __launch_bounds__(256, 2) void proj_tf32_kernel(
    const float* __restrict__ query, const float* __restrict__ value,
    const uint2* __restrict__ Wval_p, const float* __restrict__ b_val,
    const uint2* __restrict__ Woff_p, const float* __restrict__ b_off,
    const uint2* __restrict__ Wattn_p, const float* __restrict__ b_attn,
    float* __restrict__ v_out, float* __restrict__ off_out,
    float* __restrict__ attn_out, int M, int K)
{
    __shared__ float As[3][128][ASTRIDE];
    __shared__ uint2 Bs[3][8][BSTRIDE];

    const int slot = blockIdx.x;
    const float *A, *bias;
    const uint2* Bp;
    float* C;
    int N, bn;
    if (slot < 2)      { A = value; Bp = Wval_p;  bias = b_val;  C = v_out;    N = 256; bn = slot * 128; }
    else if (slot < 4) { A = query; Bp = Woff_p;  bias = b_off;  C = off_out;  N = 256; bn = (slot - 2) * 128; }
    else               { A = query; Bp = Wattn_p; bias = b_attn; C = attn_out; N = 128; bn = 0; }

    gemm_body(A, Bp, bias, C, M, N, K, blockIdx.y * 128, bn, As, Bs);
}

// ---------------- softmax + bilinear sampling ----------------
__global__ __launch_bounds__(256) void sample_kernel(
    const float* __restrict__ refp,   // [BS,LQ,4,2]
    const float* __restrict__ off,    // [BS*LQ, 256] = [H][L][P][2]
    const float* __restrict__ logits, // [BS*LQ, 128] = [H][16]
    const float* __restrict__ v,      // [BS,LQ,8,32]
    float* __restrict__ out)          // [BS*LQ, 256]
{
    __shared__ int4   s_off[HEADS][16];
    __shared__ float4 s_w[HEADS][16];

    const int bq = blockIdx.x;
    const int b = bq / LQ;
    const int h = threadIdx.x >> 5;
    const int lane = threadIdx.x & 31;
    const int j = lane & 15;          // (level,point) index

    const float* lg = logits + (size_t)bq * 128 + h * 16;
    float logit = lg[j];
    float mx = logit;
#pragma unroll
    for (int k = 8; k >= 1; k >>= 1)
        mx = fmaxf(mx, __shfl_xor_sync(0xffffffffu, mx, k, 16));
    float e = __expf(logit - mx);
    float s = e;
#pragma unroll
    for (int k = 8; k >= 1; k >>= 1)
        s += __shfl_xor_sync(0xffffffffu, s, k, 16);
    const float aw = e / s;

    const int l = j >> 2;
    const int D = 96 >> l;
    const int start = 12288 - (12288 >> (2 * l));
    const float fD = (float)D;

    const float2 r2 = ((const float2*)(refp + (size_t)bq * 8))[l];
    const float2 o2 = ((const float2*)(off + (size_t)bq * 256 + h * 32))[j];

    const float gx = fmaf(r2.x, fD, o2.x) - 0.5f;
    const float gy = fmaf(r2.y, fD, o2.y) - 0.5f;
    const float x0f = floorf(gx);
    const float y0f = floorf(gy);
    const float wx = gx - x0f;
    const float wy = gy - y0f;
    const int x0 = (int)x0f, y0 = (int)y0f;
    const int x1 = x0 + 1, y1 = y0 + 1;

    const bool vx0 = (x0 >= 0) & (x0 < D);
    const bool vx1 = (x1 >= 0) & (x1 < D);
    const bool vy0 = (y0 >= 0) & (y0 < D);
    const bool vy1 = (y1 >= 0) & (y1 < D);

    int4 o4;
    float4 w4;
    o4.x = (vx0 & vy0) ? (start + y0 * D + x0) * 256 : 0;
    o4.y = (vx1 & vy0) ? (start + y0 * D + x1) * 256 : 0;
    o4.z = (vx0 & vy1) ? (start + y1 * D + x0) * 256 : 0;
    o4.w = (vx1 & vy1) ? (start + y1 * D + x1) * 256 : 0;
    w4.x = (vx0 & vy0) ? (1.f - wx) * (1.f - wy) * aw : 0.f;
    w4.y = (vx1 & vy0) ? wx * (1.f - wy) * aw : 0.f;
    w4.z = (vx0 & vy1) ? (1.f - wx) * wy * aw : 0.f;
    w4.w = (vx1 & vy1) ? wx * wy * aw : 0.f;

    if (lane < 16) {
        s_off[h][j] = o4;
        s_w[h][j] = w4;
    }
    __syncwarp();

    const float* __restrict__ vb = v + (size_t)b * LQ * 256 + h * 32 + lane;
    float acc = 0.f;
#pragma unroll
    for (int p = 0; p < 16; p++) {
        const int4 o = s_off[h][p];
        const float4 w = s_w[h][p];
        acc = fmaf(w.x, __ldg(vb + o.x), acc);
        acc = fmaf(w.y, __ldg(vb + o.y), acc);
        acc = fmaf(w.z, __ldg(vb + o.z), acc);
        acc = fmaf(w.w, __ldg(vb + o.w), acc);
    }
    out[(size_t)bq * 256 + h * 32 + lane] = acc;
}

// ---------------- launch ----------------
extern "C" void kernel_launch(void* const* d_in, const int* in_sizes, int n_in,
                              void* d_out, int out_size)
{
    const float* query = (const float*)d_in[0];
    const float* refp  = (const float*)d_in[1];
    const float* value = (const float*)d_in[2];
    // d_in[3] = value_spatial_shapes (static, hardcoded)
    const float* W_off  = (const float*)d_in[4];
    const float* b_off  = (const float*)d_in[5];
    const float* W_attn = (const float*)d_in[6];
    const float* b_attn = (const float*)d_in[7];
    const float* W_val  = (const float*)d_in[8];
    const float* b_val  = (const float*)d_in[9];
    const float* W_out  = (const float*)d_in[10];
    const float* b_out  = (const float*)d_in[11];
    float* out = (float*)d_out;

    float *pv, *poff, *pattn, *pacc;
    uint2 *pWval, *pWoff, *pWattn, *pWout;
    cudaGetSymbolAddress((void**)&pv, g_v);
    cudaGetSymbolAddress((void**)&poff, g_off);
    cudaGetSymbolAddress((void**)&pattn, g_attn);
    cudaGetSymbolAddress((void**)&pacc, g_acc);
    cudaGetSymbolAddress((void**)&pWval, g_Wval_p);
    cudaGetSymbolAddress((void**)&pWoff, g_Woff_p);
    cudaGetSymbolAddress((void**)&pWattn, g_Wattn_p);
    cudaGetSymbolAddress((void**)&pWout, g_Wout_p);

    const int M = MTOT;
    dim3 blk(256);
    dim3 gridProj(5, (M + 127) / 128);
    dim3 gridOut(2, (M + 127) / 128);

    // pre-pack weights to paired tf32 (tiny: ~115K uint2 total)
    pack_kernel<<<(16 * 8 * 256 + 255) / 256, blk>>>(W_val, pWval, 256, 256);
    pack_kernel<<<(16 * 8 * 256 + 255) / 256, blk>>>(W_off, pWoff, 256, 256);
    pack_kernel<<<(16 * 8 * 128 + 255) / 256, blk>>>(W_attn, pWattn, 128, 256);
    pack_kernel<<<(16 * 8 * 256 + 255) / 256, blk>>>(W_out, pWout, 256, 256);

    proj_tf32_kernel<<<gridProj, blk>>>(query, value, pWval, b_val, pWoff, b_off,
                                        pWattn, b_attn, pv, poff, pattn, M, 256);
    sample_kernel<<<M, blk>>>(refp, poff, pattn, pv, pacc);
    gemm_tf32_kernel<<<gridOut, blk>>>(pacc, pWout, b_out, out, M, 256, 256);
}

// round 16
// speedup vs baseline: 1.2362x; 1.2362x over previous
#include <cuda_runtime.h>
#include <cuda_fp16.h>
#include <cstdint>
#include <math.h>

#define BS 4
#define LQ 12240
#define HEADS 8
#define MTOT (BS * LQ)   // 48960
#define KDIM 256

// ---------------- scratch (no cudaMalloc allowed) ----------------
__device__ float g_v[(size_t)MTOT * 256];
__device__ float g_off[(size_t)MTOT * 256];
__device__ float g_attn[(size_t)MTOT * 128];
__device__ float g_acc[(size_t)MTOT * 256];

// packed half2 weights: [kt 0..15][slot 0..7][n]; slot s holds (k = kt*16+2s
// in low half, k+1 in high half)
__device__ uint32_t g_Wval_p[16 * 8 * 256];
__device__ uint32_t g_Woff_p[16 * 8 * 256];
__device__ uint32_t g_Wattn_p[16 * 8 * 128];
__device__ uint32_t g_Wout_p[16 * 8 * 256];

__device__ __forceinline__ void mma_f16(float* d, const uint32_t* a, const uint32_t* b) {
    asm volatile(
        "mma.sync.aligned.m16n8k16.row.col.f32.f16.f16.f32 "
        "{%0,%1,%2,%3}, {%4,%5,%6,%7}, {%8,%9}, {%0,%1,%2,%3};"
        : "+f"(d[0]), "+f"(d[1]), "+f"(d[2]), "+f"(d[3])
        : "r"(a[0]), "r"(a[1]), "r"(a[2]), "r"(a[3]), "r"(b[0]), "r"(b[1]));
}

__device__ __forceinline__ void cp_async16(void* smem, const void* gmem) {
    uint32_t s = (uint32_t)__cvta_generic_to_shared(smem);
    asm volatile("cp.async.ca.shared.global [%0], [%1], 16;" :: "r"(s), "l"(gmem));
}

__device__ __forceinline__ uint32_t pack_h2(float lo, float hi) {
    __half2 h = __floats2half2_rn(lo, hi);   // lo -> low 16 bits
    return *(uint32_t*)&h;
}

// ---------------- weight pre-pack (one launch, 4 weights) ----------------
__global__ __launch_bounds__(256) void pack_kernel(
    const float* __restrict__ Wv, const float* __restrict__ Wo,
    const float* __restrict__ Wa, const float* __restrict__ Wu,
    uint32_t* __restrict__ Pv, uint32_t* __restrict__ Po,
    uint32_t* __restrict__ Pa, uint32_t* __restrict__ Pu)
{
    const float* W; uint32_t* P; int N;
    switch (blockIdx.y) {
        case 0: W = Wv; P = Pv; N = 256; break;
        case 1: W = Wo; P = Po; N = 256; break;
        case 2: W = Wa; P = Pa; N = 128; break;
        default: W = Wu; P = Pu; N = 256; break;
    }
    const int idx = blockIdx.x * 256 + threadIdx.x;
    if (idx >= 16 * 8 * N) return;
    const int n = idx % N;
    const int s = (idx / N) & 7;
    const int kt = idx / (N * 8);
    const int k = kt * 16 + 2 * s;
    P[idx] = pack_h2(W[(size_t)k * N + n], W[(size_t)(k + 1) * N + n]);
}

#define ASTRIDE 24     // A floats per row (16 + 8 pad): LDS.64 bank 12g+tig, distinct
#define BSTRIDE 136    // B uint per slot row (128 + 8 pad): bank 8*tig+g, distinct

// smem stage sizes
#define A_STAGE (128 * ASTRIDE)          // floats
#define B_STAGE (8 * BSTRIDE)            // uints
#define SMEM_BYTES (3 * A_STAGE * 4 + 3 * B_STAGE * 4)   // 36864 + 13056 = 49920

// ---------------- fp16 tensor-core GEMM body ----------------
// Block tile 128x128, 8 warps 4(M) x 2(N), warp 32x64 = 2x8 m16n8k16 tiles.
// A: cp.async raw fp32, cvt to half2 at fragment load.
// B: cp.async pre-packed half2 (only this CTA's 128-col half).
__device__ __forceinline__ void gemm_body(
    const float* __restrict__ A, const uint32_t* __restrict__ Bp,
    const float* __restrict__ bias, float* __restrict__ C,
    int M, int N, int bm, int bn)
{
    extern __shared__ char smem[];
    float (*As)[128][ASTRIDE] = (float (*)[128][ASTRIDE])smem;
    uint32_t (*Bs)[8][BSTRIDE] = (uint32_t (*)[8][BSTRIDE])(smem + 3 * A_STAGE * 4);

    const int tid = threadIdx.x;
    const int warp = tid >> 5;
    const int lane = tid & 31;
    const int wm = (warp >> 1) * 32;
    const int wn = (warp & 1) * 64;
    const int g = lane >> 2;           // 0..7
    const int tig = lane & 3;          // 0..3

    // A fill: thread cp.asyncs 32B of row (tid>>1) at k-offset (tid&1)*8
    const int a_row = tid >> 1;
    const int a_half = tid & 1;
    int a_grow = bm + a_row; if (a_grow >= M) a_grow = M - 1;
    const float* Ag = A + (size_t)a_grow * KDIM + a_half * 8;

    // B fill: slot = tid>>5, 4 uint at (lane*4) within this CTA's 128 cols
    const int b_slot = tid >> 5;
    const int b_pos = lane * 4;
    const uint32_t* Bg = Bp + (size_t)b_slot * N + bn + b_pos;

#define FILL(kt, stg) do { \
        const float* ap = Ag + (kt) * 16; \
        cp_async16(&As[stg][a_row][a_half * 8], ap); \
        cp_async16(&As[stg][a_row][a_half * 8 + 4], ap + 4); \
        cp_async16(&Bs[stg][b_slot][b_pos], Bg + (size_t)(kt) * 8 * N); \
        asm volatile("cp.async.commit_group;"); \
    } while (0)

    float acc[2][8][4];
#pragma unroll
    for (int i = 0; i < 2; i++)
#pragma unroll
        for (int j = 0; j < 8; j++)
#pragma unroll
            for (int r = 0; r < 4; r++) acc[i][j][r] = 0.f;

    const int NT = KDIM / 16;   // 16
    FILL(0, 0);
    FILL(1, 1);

    int st = 0;
    for (int kt = 0; kt < NT; kt++) {
        if (kt + 1 < NT) {
            asm volatile("cp.async.wait_group 1;");
        } else {
            asm volatile("cp.async.wait_group 0;");
        }
        __syncthreads();

        if (kt + 2 < NT) {
            int fs = st - 1; if (fs < 0) fs += 3;   // (kt+2) % 3
            FILL(kt + 2, fs);
        }

        // fragments: m16n8k16 fp16
        uint32_t af[2][4];
#pragma unroll
        for (int mt = 0; mt < 2; mt++) {
            const int mb = wm + mt * 16;
            float2 f0 = *(const float2*)&As[st][mb + g][2 * tig];
            float2 f1 = *(const float2*)&As[st][mb + g + 8][2 * tig];
            float2 f2 = *(const float2*)&As[st][mb + g][2 * tig + 8];
            float2 f3 = *(const float2*)&As[st][mb + g + 8][2 * tig + 8];
            af[mt][0] = pack_h2(f0.x, f0.y);
            af[mt][1] = pack_h2(f1.x, f1.y);
            af[mt][2] = pack_h2(f2.x, f2.y);
            af[mt][3] = pack_h2(f3.x, f3.y);
        }
        uint32_t bf[8][2];
#pragma unroll
        for (int nt = 0; nt < 8; nt++) {
            const int n = wn + nt * 8 + g;
            bf[nt][0] = Bs[st][tig][n];
            bf[nt][1] = Bs[st][tig + 4][n];
        }
#pragma unroll
        for (int mt = 0; mt < 2; mt++)
#pragma unroll
            for (int nt = 0; nt < 8; nt++)
                mma_f16(acc[mt][nt], af[mt], bf[nt]);

        st = st + 1 == 3 ? 0 : st + 1;
    }

    // epilogue: D + bias -> C
#pragma unroll
    for (int nt = 0; nt < 8; nt++) {
        const int n = bn + wn + nt * 8 + 2 * tig;
        const float b0 = bias[n];
        const float b1 = bias[n + 1];
#pragma unroll
        for (int mt = 0; mt < 2; mt++) {
            const int m0 = bm + wm + mt * 16 + g;
            if (m0 < M) {
                float2 o = make_float2(acc[mt][nt][0] + b0, acc[mt][nt][1] + b1);
                *(float2*)&C[(size_t)m0 * N + n] = o;
            }
            const int m1 = m0 + 8;
            if (m1 < M) {
                float2 o = make_float2(acc[mt][nt][2] + b0, acc[mt][nt][3] + b1);
                *(float2*)&C[(size_t)m1 * N + n] = o;
            }
        }
    }
#undef FILL
}

// Output projection.
__global__ __launch_bounds__(256, 2) void gemm_f16_kernel(
    const float* __restrict__ A, const uint32_t* __restrict__ Bp,
    const float* __restrict__ bias, float* __restrict__ C, int M, int N)
{
    gemm_body(A, Bp, bias, C, M, N, blockIdx.y * 128, blockIdx.x * 128);
}

// Merged projections: slots 0-1 v, 2-3 off, 4 attn.
__global__ __launch_bounds__(256, 2) void proj_f16_kernel(
    const float* __restrict__ query, const float* __restrict__ value,
    const uint32_t* __restrict__ Pv, const float* __restrict__ b_val,
    const uint32_t* __restrict__ Po, const float* __restrict__ b_off,
    const uint32_t* __restrict__ Pa, const float* __restrict__ b_attn,
    float* __restrict__ v_out, float* __restrict__ off_out,
    float* __restrict__ attn_out, int M)
{
    const int slot = blockIdx.x;
    const float *A, *bias;
    const uint32_t* Bp;
    float* C;
    int N, bn;
    if (slot < 2)      { A = value; Bp = Pv; bias = b_val;  C = v_out;    N = 256; bn = slot * 128; }
    else if (slot < 4) { A = query; Bp = Po; bias = b_off;  C = off_out;  N = 256; bn = (slot - 2) * 128; }
    else               { A = query; Bp = Pa; bias = b_attn; C = attn_out; N = 128; bn = 0; }

    gemm_body(A, Bp, bias, C, M, N, blockIdx.y * 128, bn);
}

// ---------------- softmax + bilinear sampling (L1-floor, unchanged) --------
__global__ __launch_bounds__(256) void sample_kernel(
    const float* __restrict__ refp, const float* __restrict__ off,
    const float* __restrict__ logits, const float* __restrict__ v,
    float* __restrict__ out)
{
    __shared__ int4   s_off[HEADS][16];
    __shared__ float4 s_w[HEADS][16];

    const int bq = blockIdx.x;
    const int b = bq / LQ;
    const int h = threadIdx.x >> 5;
    const int lane = threadIdx.x & 31;
    const int j = lane & 15;

    const float* lg = logits + (size_t)bq * 128 + h * 16;
    float logit = lg[j];
    float mx = logit;
#pragma unroll
    for (int k = 8; k >= 1; k >>= 1)
        mx = fmaxf(mx, __shfl_xor_sync(0xffffffffu, mx, k, 16));
    float e = __expf(logit - mx);
    float s = e;
#pragma unroll
    for (int k = 8; k >= 1; k >>= 1)
        s += __shfl_xor_sync(0xffffffffu, s, k, 16);
    const float aw = e / s;

    const int l = j >> 2;
    const int D = 96 >> l;
    const int start = 12288 - (12288 >> (2 * l));
    const float fD = (float)D;

    const float2 r2 = ((const float2*)(refp + (size_t)bq * 8))[l];
    const float2 o2 = ((const float2*)(off + (size_t)bq * 256 + h * 32))[j];

    const float gx = fmaf(r2.x, fD, o2.x) - 0.5f;
    const float gy = fmaf(r2.y, fD, o2.y) - 0.5f;
    const float x0f = floorf(gx);
    const float y0f = floorf(gy);
    const float wx = gx - x0f;
    const float wy = gy - y0f;
    const int x0 = (int)x0f, y0 = (int)y0f;
    const int x1 = x0 + 1, y1 = y0 + 1;

    const bool vx0 = (x0 >= 0) & (x0 < D);
    const bool vx1 = (x1 >= 0) & (x1 < D);
    const bool vy0 = (y0 >= 0) & (y0 < D);
    const bool vy1 = (y1 >= 0) & (y1 < D);

    int4 o4;
    float4 w4;
    o4.x = (vx0 & vy0) ? (start + y0 * D + x0) * 256 : 0;
    o4.y = (vx1 & vy0) ? (start + y0 * D + x1) * 256 : 0;
    o4.z = (vx0 & vy1) ? (start + y1 * D + x0) * 256 : 0;
    o4.w = (vx1 & vy1) ? (start + y1 * D + x1) * 256 : 0;
    w4.x = (vx0 & vy0) ? (1.f - wx) * (1.f - wy) * aw : 0.f;
    w4.y = (vx1 & vy0) ? wx * (1.f - wy) * aw : 0.f;
    w4.z = (vx0 & vy1) ? (1.f - wx) * wy * aw : 0.f;
    w4.w = (vx1 & vy1) ? wx * wy * aw : 0.f;

    if (lane < 16) {
        s_off[h][j] = o4;
        s_w[h][j] = w4;
    }
    __syncwarp();

    const float* __restrict__ vb = v + (size_t)b * LQ * 256 + h * 32 + lane;
    float acc = 0.f;
#pragma unroll
    for (int p = 0; p < 16; p++) {
        const int4 o = s_off[h][p];
        const float4 w = s_w[h][p];
        acc = fmaf(w.x, __ldg(vb + o.x), acc);
        acc = fmaf(w.y, __ldg(vb + o.y), acc);
        acc = fmaf(w.z, __ldg(vb + o.z), acc);
        acc = fmaf(w.w, __ldg(vb + o.w), acc);
    }
    out[(size_t)bq * 256 + h * 32 + lane] = acc;
}

// ---------------- launch ----------------
extern "C" void kernel_launch(void* const* d_in, const int* in_sizes, int n_in,
                              void* d_out, int out_size)
{
    const float* query = (const float*)d_in[0];
    const float* refp  = (const float*)d_in[1];
    const float* value = (const float*)d_in[2];
    const float* W_off  = (const float*)d_in[4];
    const float* b_off  = (const float*)d_in[5];
    const float* W_attn = (const float*)d_in[6];
    const float* b_attn = (const float*)d_in[7];
    const float* W_val  = (const float*)d_in[8];
    const float* b_val  = (const float*)d_in[9];
    const float* W_out  = (const float*)d_in[10];
    const float* b_out  = (const float*)d_in[11];
    float* out = (float*)d_out;

    float *pv, *poff, *pattn, *pacc;
    uint32_t *pWval, *pWoff, *pWattn, *pWout;
    cudaGetSymbolAddress((void**)&pv, g_v);
    cudaGetSymbolAddress((void**)&poff, g_off);
    cudaGetSymbolAddress((void**)&pattn, g_attn);
    cudaGetSymbolAddress((void**)&pacc, g_acc);
    cudaGetSymbolAddress((void**)&pWval, g_Wval_p);
    cudaGetSymbolAddress((void**)&pWoff, g_Woff_p);
    cudaGetSymbolAddress((void**)&pWattn, g_Wattn_p);
    cudaGetSymbolAddress((void**)&pWout, g_Wout_p);

    cudaFuncSetAttribute(proj_f16_kernel, cudaFuncAttributeMaxDynamicSharedMemorySize, SMEM_BYTES);
    cudaFuncSetAttribute(gemm_f16_kernel, cudaFuncAttributeMaxDynamicSharedMemorySize, SMEM_BYTES);

    const int M = MTOT;
    dim3 blk(256);
    const int MB = (M + 127) / 128;   // 383

    pack_kernel<<<dim3(128, 4), blk>>>(W_val, W_off, W_attn, W_out,
                                       pWval, pWoff, pWattn, pWout);
    proj_f16_kernel<<<dim3(5, MB), blk, SMEM_BYTES>>>(query, value, pWval, b_val,
                                                      pWoff, b_off, pWattn, b_attn,
                                                      pv, poff, pattn, M);
    sample_kernel<<<M, blk>>>(refp, poff, pattn, pv, pacc);
    gemm_f16_kernel<<<dim3(2, MB), blk, SMEM_BYTES>>>(pacc, pWout, b_out, out, M, 256);
}